// round 12
// baseline (speedup 1.0000x reference)
#include <cuda_runtime.h>
#include <cuda_bf16.h>
#include <cuda_fp16.h>
#include <cstdint>

// SO3Conv via fp16 2-term split HMMA GEMM — compute_103-safe.
// prep:   W2T_l[j][k] = psi (UNSCALED), split to fp16 hi/lo
// repack: X_l[r=b*d+m][k=f*d+u] = fp16(x[b,f,off+u*d+m])
// gemm:   CTA 256x64, 8 warps, 2-stage cp.async, Y = Xh*(Wh+Wl), *= scale_l

#define IRREP 455

__device__ __align__(16) __half g_Xh[29818880];   // 65536*455
__device__ __align__(16) __half g_Wh[1863680];    // 4096*455
__device__ __align__(16) __half g_Wl[1863680];

__constant__ int c_off[7] = {0, 1, 10, 35, 84, 165, 286};
__constant__ int c_d[7]   = {1, 3, 5, 7, 9, 11, 13};

// gemm tile tables, DESCENDING d (q=0..6 -> l=6..0). blocks per l = 4*d*d.
__constant__ int P_CUM[8] = {0, 676, 1160, 1484, 1680, 1780, 1816, 1820};
__constant__ int P_D[7]   = {13, 11, 9, 7, 5, 3, 1};
__constant__ int P_OFF[7] = {286, 165, 84, 35, 10, 1, 0};

// ---------------------------------------------------------------------------
// PTX helpers
// ---------------------------------------------------------------------------
__device__ __forceinline__ uint32_t smem_u32(const void* p) {
    uint32_t a;
    asm("{ .reg .u64 t; cvta.to.shared.u64 t, %1; cvt.u32.u64 %0, t; }" : "=r"(a) : "l"(p));
    return a;
}
__device__ __forceinline__ void cpasync16(uint32_t s, const void* g) {
    asm volatile("cp.async.cg.shared.global [%0], [%1], 16;" :: "r"(s), "l"(g));
}
#define CP_COMMIT() asm volatile("cp.async.commit_group;" ::: "memory")
#define CP_WAIT0()  asm volatile("cp.async.wait_group 0;" ::: "memory")

__device__ __forceinline__ void ldsm_x4(uint32_t* r, uint32_t addr) {
    asm volatile("ldmatrix.sync.aligned.m8n8.x4.shared.b16 {%0,%1,%2,%3}, [%4];"
        : "=r"(r[0]), "=r"(r[1]), "=r"(r[2]), "=r"(r[3]) : "r"(addr));
}
__device__ __forceinline__ void mma16816(float* c, const uint32_t* a, const uint32_t* b) {
    asm volatile("mma.sync.aligned.m16n8k16.row.col.f32.f16.f16.f32 "
        "{%0,%1,%2,%3}, {%4,%5,%6,%7}, {%8,%9}, {%0,%1,%2,%3};"
        : "+f"(c[0]), "+f"(c[1]), "+f"(c[2]), "+f"(c[3])
        : "r"(a[0]), "r"(a[1]), "r"(a[2]), "r"(a[3]), "r"(b[0]), "r"(b[1]));
}

// smem XOR swizzle: row stride 64B, 16B chunk c -> c ^ ((row>>1)&3)
__device__ __forceinline__ uint32_t swz(int row, int c) {
    return (uint32_t)(row * 64 + ((c ^ ((row >> 1) & 3)) << 4));
}
__device__ __forceinline__ uint32_t pack_h2(__half a, __half b) {
    return (uint32_t)__half_as_ushort(a) | ((uint32_t)__half_as_ushort(b) << 16);
}

// ---------------------------------------------------------------------------
// repack body, templated on D (all divides compile-time). Single fp16 plane.
// ---------------------------------------------------------------------------
template <int DD>
__device__ __forceinline__ void repack_body(const float* __restrict__ x, int b,
                                            int off, char* sm) {
    constexpr int d2 = DD * DD;
    constexpr int Kl = 64 * DD;
    float* xs = (float*)sm;
    const int tid = threadIdx.x;

    for (int t = tid; t < 64 * d2; t += 256) {
        int f = t / d2, s = t - f * d2;
        xs[t] = x[((b << 6) + f) * IRREP + off + s];
    }
    __syncthreads();

    const long Xbase = 65536L * off;
    constexpr int slots = 16 * d2;   // groups of 4 k
    for (int t = tid; t < slots; t += 256) {
        int m  = t / (16 * DD);
        int kg = t - m * (16 * DD);
        int k  = kg * 4;
        uint32_t H[2];
#pragma unroll
        for (int p = 0; p < 2; p++) {
            int ki = k + 2 * p;
            int f0 = ki / DD,       u0 = ki - f0 * DD;
            int f1 = (ki + 1) / DD, u1 = (ki + 1) - f1 * DD;
            H[p] = pack_h2(__float2half(xs[f0 * d2 + u0 * DD + m]),
                           __float2half(xs[f1 * d2 + u1 * DD + m]));
        }
        long idx = Xbase + (long)(b * DD + m) * Kl + k;
        *(uint2*)(g_Xh + idx) = make_uint2(H[0], H[1]);
    }
}

// ---------------------------------------------------------------------------
// Fused prepare kernel: [0,512) prep | [512,7680) repack
// ---------------------------------------------------------------------------
__global__ void __launch_bounds__(256) prepare_kernel(const float* __restrict__ x,
                                                      const float* __restrict__ Dm,
                                                      const float* __restrict__ w) {
    extern __shared__ __align__(16) char sm[];
    const int tid = threadIdx.x;
    const int bid = blockIdx.x;

    if (bid < 512) {
        // ---- prep: psi GEMM (4096 fg x 455 i, K=64) -> W2T fp16 hi/lo, UNSCALED ----
        float (*Wsh)[65] = (float (*)[65])sm;
        float (*Dsh)[65] = (float (*)[65])(sm + 64 * 65 * 4);

        const int tx = tid & 15;
        const int ty = tid >> 4;
        const int i0  = (bid & 7) * 64;
        const int fg0 = (bid >> 3) * 64;

        for (int t = tid; t < 64 * 64; t += 256) {
            int r = t >> 6, n = t & 63;
            Wsh[r][n] = w[(fg0 + r) * 64 + n];
        }
        for (int t = tid; t < 64 * 64; t += 256) {
            int n = t >> 6, ii = t & 63;
            int i = i0 + ii;
            Dsh[n][ii] = (i < IRREP) ? Dm[n * IRREP + i] : 0.0f;
        }
        __syncthreads();

        float acc[4][4];
#pragma unroll
        for (int a = 0; a < 4; a++)
#pragma unroll
            for (int b = 0; b < 4; b++) acc[a][b] = 0.0f;

#pragma unroll 8
        for (int n = 0; n < 64; n++) {
            float wa[4], db[4];
#pragma unroll
            for (int a = 0; a < 4; a++) wa[a] = Wsh[ty + 16 * a][n];
#pragma unroll
            for (int b = 0; b < 4; b++) db[b] = Dsh[n][tx + 16 * b];
#pragma unroll
            for (int a = 0; a < 4; a++)
#pragma unroll
                for (int b = 0; b < 4; b++) acc[a][b] += wa[a] * db[b];
        }

#pragma unroll
        for (int a = 0; a < 4; a++) {
            int fg = fg0 + ty + 16 * a;
            int f = fg >> 6, g = fg & 63;
#pragma unroll
            for (int b = 0; b < 4; b++) {
                int i = i0 + tx + 16 * b;
                if (i >= IRREP) continue;
                int l = 6;
#pragma unroll
                for (int q = 6; q >= 1; q--)
                    if (i < c_off[q]) l = q - 1;
                int d = c_d[l], off = c_off[l];
                int r = i - off;
                int u = r / d, v = r - u * d;
                float val = acc[a][b];          // UNSCALED (scale in gemm epilogue)
                __half h = __float2half(val);
                __half lo = __float2half(val - __half2float(h));
                long idx = 4096L * off + (long)(g * d + v) * (64 * d) + (f * d + u);
                g_Wh[idx] = h;
                g_Wl[idx] = lo;
            }
        }
    } else {
        const int rel = bid - 512;
        const int l = 6 - (rel >> 10);            // descending d
        const int b = rel & 1023;
        switch (l) {
            case 6: repack_body<13>(x, b, 286, sm); break;
            case 5: repack_body<11>(x, b, 165, sm); break;
            case 4: repack_body<9> (x, b, 84,  sm); break;
            case 3: repack_body<7> (x, b, 35,  sm); break;
            case 2: repack_body<5> (x, b, 10,  sm); break;
            case 1: repack_body<3> (x, b, 1,   sm); break;
            default: repack_body<1>(x, b, 0,   sm); break;
        }
    }
}

// ---------------------------------------------------------------------------
// gemm: CTA = 256 rows x 64 cols, 8 warps (64x32 each), K chunks of 32,
// 2-stage cp.async, XOR-swizzled smem, fp16 2-term (A x (Bh + Bl)).
// per stage: A 16384 | Bh 4096 | Bl 4096 = 24576; x2 = 49152.
// ---------------------------------------------------------------------------
#define ST      24576
#define OFF_A   0
#define OFF_BH  16384
#define OFF_BL  20480
#define SM_TOT  (2 * ST)   // 49152

__global__ void __launch_bounds__(256, 2) gemm_kernel(float* __restrict__ out) {
    extern __shared__ __align__(16) char smem[];
    const uint32_t sbase = smem_u32(smem);
    __shared__ int lutS[64];

    const int tid = threadIdx.x;
    const int lane = tid & 31;
    const int wid = tid >> 5;
    const int wm = wid >> 1;      // 0..3 : 64-row band
    const int wn = wid & 1;       // 0..1 : 32-col band

    const int bid = blockIdx.x;
    int q = 0;
#pragma unroll
    for (int t = 1; t < 7; t++)
        if (bid >= P_CUM[t]) q = t;
    const int rel = bid - P_CUM[q];
    const int d  = P_D[q];
    const int off = P_OFF[q];
    const int Kl = 64 * d;
    const int bt = rel / d;
    const int jt = rel - bt * d;
    const int R0 = bt * 256;
    const int j0 = jt * 64;
    const int nc = 2 * d;
    const float scale = 0.125f * rsqrtf(64.0f * (float)d);

    // inline LUT: column j0+jj -> g*455 + v*d + off
    if (tid < 64) {
        int j = j0 + tid;
        int g = j / d, v = j - g * d;
        lutS[tid] = g * IRREP + v * d + off;
    }

    const int rr = tid >> 2;     // 0..63
    const int cc = tid & 3;      // 16B chunk

    // persistent load pointers (advance +32 halfs per issued chunk)
    const __half* pA[4];
    const __half* pBh;
    const __half* pBl;
    {
        const __half* Xh = g_Xh + 65536L * off;
        const __half* Wh = g_Wh + 4096L * off;
        const __half* Wl = g_Wl + 4096L * off;
#pragma unroll
        for (int i = 0; i < 4; i++)
            pA[i] = Xh + (long)(R0 + rr + 64 * i) * Kl + cc * 8;
        long gofs = (long)(j0 + rr) * Kl + cc * 8;
        pBh = Wh + gofs;
        pBl = Wl + gofs;
    }
    uint32_t soA[4];
#pragma unroll
    for (int i = 0; i < 4; i++) soA[i] = swz(rr + 64 * i, cc);
    const uint32_t soB = swz(rr, cc);

    // ldmatrix addresses at ks=0 (stage-relative); ks=1 -> ^32
    uint32_t addrA0[4], addrB0[2];
#pragma unroll
    for (int mf = 0; mf < 4; mf++) {
        int row = wm * 64 + mf * 16 + (lane & 15);
        addrA0[mf] = swz(row, (lane >> 4) & 1);
    }
#pragma unroll
    for (int nn = 0; nn < 2; nn++) {
        int row = wn * 32 + nn * 16 + ((lane >> 3) & 2) * 4 + (lane & 7);
        addrB0[nn] = swz(row, (lane >> 3) & 1);
    }

    float acc[4][4][4];
#pragma unroll
    for (int mf = 0; mf < 4; mf++)
#pragma unroll
        for (int ns = 0; ns < 4; ns++)
#pragma unroll
            for (int i = 0; i < 4; i++) acc[mf][ns][i] = 0.0f;

#define ISSUE_CHUNK(s)                                                   \
    do {                                                                 \
        uint32_t sb_ = sbase + (uint32_t)((s) * ST);                     \
        cpasync16(sb_ + OFF_A + soA[0], pA[0]); pA[0] += 32;             \
        cpasync16(sb_ + OFF_A + soA[1], pA[1]); pA[1] += 32;             \
        cpasync16(sb_ + OFF_A + soA[2], pA[2]); pA[2] += 32;             \
        cpasync16(sb_ + OFF_A + soA[3], pA[3]); pA[3] += 32;             \
        cpasync16(sb_ + OFF_BH + soB, pBh); pBh += 32;                   \
        cpasync16(sb_ + OFF_BL + soB, pBl); pBl += 32;                   \
        CP_COMMIT();                                                     \
    } while (0)

    // prologue: chunk 0 into stage 0
    ISSUE_CHUNK(0);

    for (int c = 0; c < nc; c++) {
        CP_WAIT0();
        __syncthreads();   // chunk c visible; all warps done reading stage (c+1)&1

        if (c + 1 < nc) ISSUE_CHUNK((c + 1) & 1);   // overlaps with compute below

        const uint32_t sb = sbase + (uint32_t)((c & 1) * ST);
#pragma unroll
        for (int ks = 0; ks < 2; ks++) {
            const uint32_t kx = (uint32_t)(ks * 32);   // XOR, not add
            uint32_t a[4][4], bh[2][4], bl[2][4];
#pragma unroll
            for (int mf = 0; mf < 4; mf++) ldsm_x4(a[mf], sb + OFF_A + (addrA0[mf] ^ kx));
#pragma unroll
            for (int nn = 0; nn < 2; nn++) ldsm_x4(bh[nn], sb + OFF_BH + (addrB0[nn] ^ kx));
#pragma unroll
            for (int nn = 0; nn < 2; nn++) ldsm_x4(bl[nn], sb + OFF_BL + (addrB0[nn] ^ kx));

#pragma unroll
            for (int mf = 0; mf < 4; mf++)
#pragma unroll
                for (int ns = 0; ns < 4; ns++)
                    mma16816(acc[mf][ns], a[mf], &bh[ns >> 1][(ns & 1) * 2]);
#pragma unroll
            for (int mf = 0; mf < 4; mf++)
#pragma unroll
                for (int ns = 0; ns < 4; ns++)
                    mma16816(acc[mf][ns], a[mf], &bl[ns >> 1][(ns & 1) * 2]);
        }
        __syncthreads();
    }

    // ---- epilogue: scale + scatter via LUT ----
#pragma unroll
    for (int mf = 0; mf < 4; mf++) {
        int row0 = R0 + wm * 64 + mf * 16 + (lane >> 2);
        int row1 = row0 + 8;
        int b0 = row0 / d, m0 = row0 - b0 * d;
        int b1 = row1 / d, m1 = row1 - b1 * d;
        long ob0 = (long)b0 * 29120 + m0;
        long ob1 = (long)b1 * 29120 + m1;
#pragma unroll
        for (int ns = 0; ns < 4; ns++) {
            int j = wn * 32 + ns * 8 + (lane & 3) * 2;
            int o0 = lutS[j], o1 = lutS[j + 1];
            out[ob0 + o0] = acc[mf][ns][0] * scale;
            out[ob0 + o1] = acc[mf][ns][1] * scale;
            out[ob1 + o0] = acc[mf][ns][2] * scale;
            out[ob1 + o1] = acc[mf][ns][3] * scale;
        }
    }
}

// ---------------------------------------------------------------------------
extern "C" void kernel_launch(void* const* d_in, const int* in_sizes, int n_in,
                              void* d_out, int out_size) {
    const float* x  = (const float*)d_in[0];
    const float* Dm = (const float*)d_in[1];
    const float* w  = (const float*)d_in[2];
    float* out = (float*)d_out;

    cudaFuncSetAttribute(prepare_kernel, cudaFuncAttributeMaxDynamicSharedMemorySize, 46912);
    cudaFuncSetAttribute(gemm_kernel, cudaFuncAttributeMaxDynamicSharedMemorySize, SM_TOT);

    prepare_kernel<<<7680, 256, 46912>>>(x, Dm, w);
    gemm_kernel<<<1820, 256, SM_TOT>>>(out);
}

// round 13
// speedup vs baseline: 1.4556x; 1.4556x over previous
#include <cuda_runtime.h>
#include <cuda_bf16.h>
#include <cuda_fp16.h>
#include <cstdint>

// SO3Conv via single-term fp16 HMMA GEMM — compute_103-safe.
// prep:   W2T_l[j][k] = fp16(psi), UNSCALED (~N(0,1))
// repack: X_l[r=b*d+m][k=f*d+u] = fp16(x[b,f,off+u*d+m])
// gemm:   Y[r][j] = sum_k Xh[r][k]*Wh[j][k]; epilogue *= scale_l
//         CTA 128x64, 4 warps, K-chunk 64, 2-stage cp.async.

#define IRREP 455

__device__ __align__(16) __half g_Xh[29818880];   // 65536*455
__device__ __align__(16) __half g_Wh[1863680];    // 4096*455

__constant__ int c_off[7] = {0, 1, 10, 35, 84, 165, 286};
__constant__ int c_d[7]   = {1, 3, 5, 7, 9, 11, 13};

// gemm tile tables, DESCENDING d (q=0..6 -> l=6..0). blocks per l = 8*d*d.
__constant__ int P_CUM[8] = {0, 1352, 2320, 2968, 3360, 3560, 3632, 3640};
__constant__ int P_D[7]   = {13, 11, 9, 7, 5, 3, 1};
__constant__ int P_OFF[7] = {286, 165, 84, 35, 10, 1, 0};

// ---------------------------------------------------------------------------
// PTX helpers
// ---------------------------------------------------------------------------
__device__ __forceinline__ uint32_t smem_u32(const void* p) {
    uint32_t a;
    asm("{ .reg .u64 t; cvta.to.shared.u64 t, %1; cvt.u32.u64 %0, t; }" : "=r"(a) : "l"(p));
    return a;
}
__device__ __forceinline__ void cpasync16(uint32_t s, const void* g) {
    asm volatile("cp.async.cg.shared.global [%0], [%1], 16;" :: "r"(s), "l"(g));
}
#define CP_COMMIT() asm volatile("cp.async.commit_group;" ::: "memory")
#define CP_WAIT0()  asm volatile("cp.async.wait_group 0;" ::: "memory")

__device__ __forceinline__ void ldsm_x4(uint32_t* r, uint32_t addr) {
    asm volatile("ldmatrix.sync.aligned.m8n8.x4.shared.b16 {%0,%1,%2,%3}, [%4];"
        : "=r"(r[0]), "=r"(r[1]), "=r"(r[2]), "=r"(r[3]) : "r"(addr));
}
__device__ __forceinline__ void mma16816(float* c, const uint32_t* a, const uint32_t* b) {
    asm volatile("mma.sync.aligned.m16n8k16.row.col.f32.f16.f16.f32 "
        "{%0,%1,%2,%3}, {%4,%5,%6,%7}, {%8,%9}, {%0,%1,%2,%3};"
        : "+f"(c[0]), "+f"(c[1]), "+f"(c[2]), "+f"(c[3])
        : "r"(a[0]), "r"(a[1]), "r"(a[2]), "r"(a[3]), "r"(b[0]), "r"(b[1]));
}

// smem swizzle for 128B rows: 16B chunk c (0..7) -> c ^ (row & 7)
__device__ __forceinline__ uint32_t swz128(int row, int c) {
    return (uint32_t)(row * 128 + ((c ^ (row & 7)) << 4));
}
__device__ __forceinline__ uint32_t pack_h2(__half a, __half b) {
    return (uint32_t)__half_as_ushort(a) | ((uint32_t)__half_as_ushort(b) << 16);
}

// ---------------------------------------------------------------------------
// repack body, templated on D (all divides compile-time). Single fp16 plane.
// ---------------------------------------------------------------------------
template <int DD>
__device__ __forceinline__ void repack_body(const float* __restrict__ x, int b,
                                            int off, char* sm) {
    constexpr int d2 = DD * DD;
    constexpr int Kl = 64 * DD;
    float* xs = (float*)sm;
    const int tid = threadIdx.x;

    for (int t = tid; t < 64 * d2; t += 256) {
        int f = t / d2, s = t - f * d2;
        xs[t] = x[((b << 6) + f) * IRREP + off + s];
    }
    __syncthreads();

    const long Xbase = 65536L * off;
    constexpr int slots = 16 * d2;   // groups of 4 k
    for (int t = tid; t < slots; t += 256) {
        int m  = t / (16 * DD);
        int kg = t - m * (16 * DD);
        int k  = kg * 4;
        uint32_t H[2];
#pragma unroll
        for (int p = 0; p < 2; p++) {
            int ki = k + 2 * p;
            int f0 = ki / DD,       u0 = ki - f0 * DD;
            int f1 = (ki + 1) / DD, u1 = (ki + 1) - f1 * DD;
            H[p] = pack_h2(__float2half(xs[f0 * d2 + u0 * DD + m]),
                           __float2half(xs[f1 * d2 + u1 * DD + m]));
        }
        long idx = Xbase + (long)(b * DD + m) * Kl + k;
        *(uint2*)(g_Xh + idx) = make_uint2(H[0], H[1]);
    }
}

// ---------------------------------------------------------------------------
// Fused prepare kernel: [0,512) prep | [512,7680) repack
// ---------------------------------------------------------------------------
__global__ void __launch_bounds__(256) prepare_kernel(const float* __restrict__ x,
                                                      const float* __restrict__ Dm,
                                                      const float* __restrict__ w) {
    extern __shared__ __align__(16) char sm[];
    const int tid = threadIdx.x;
    const int bid = blockIdx.x;

    if (bid < 512) {
        // ---- prep: psi GEMM (4096 fg x 455 i, K=64) -> W2T fp16, UNSCALED ----
        float (*Wsh)[65] = (float (*)[65])sm;
        float (*Dsh)[65] = (float (*)[65])(sm + 64 * 65 * 4);

        const int tx = tid & 15;
        const int ty = tid >> 4;
        const int i0  = (bid & 7) * 64;
        const int fg0 = (bid >> 3) * 64;

        for (int t = tid; t < 64 * 64; t += 256) {
            int r = t >> 6, n = t & 63;
            Wsh[r][n] = w[(fg0 + r) * 64 + n];
        }
        for (int t = tid; t < 64 * 64; t += 256) {
            int n = t >> 6, ii = t & 63;
            int i = i0 + ii;
            Dsh[n][ii] = (i < IRREP) ? Dm[n * IRREP + i] : 0.0f;
        }
        __syncthreads();

        float acc[4][4];
#pragma unroll
        for (int a = 0; a < 4; a++)
#pragma unroll
            for (int b = 0; b < 4; b++) acc[a][b] = 0.0f;

#pragma unroll 8
        for (int n = 0; n < 64; n++) {
            float wa[4], db[4];
#pragma unroll
            for (int a = 0; a < 4; a++) wa[a] = Wsh[ty + 16 * a][n];
#pragma unroll
            for (int b = 0; b < 4; b++) db[b] = Dsh[n][tx + 16 * b];
#pragma unroll
            for (int a = 0; a < 4; a++)
#pragma unroll
                for (int b = 0; b < 4; b++) acc[a][b] += wa[a] * db[b];
        }

#pragma unroll
        for (int a = 0; a < 4; a++) {
            int fg = fg0 + ty + 16 * a;
            int f = fg >> 6, g = fg & 63;
#pragma unroll
            for (int b = 0; b < 4; b++) {
                int i = i0 + tx + 16 * b;
                if (i >= IRREP) continue;
                int l = 6;
#pragma unroll
                for (int q = 6; q >= 1; q--)
                    if (i < c_off[q]) l = q - 1;
                int d = c_d[l], off = c_off[l];
                int r = i - off;
                int u = r / d, v = r - u * d;
                long idx = 4096L * off + (long)(g * d + v) * (64 * d) + (f * d + u);
                g_Wh[idx] = __float2half(acc[a][b]);   // UNSCALED
            }
        }
    } else {
        const int rel = bid - 512;
        const int l = 6 - (rel >> 10);            // descending d
        const int b = rel & 1023;
        switch (l) {
            case 6: repack_body<13>(x, b, 286, sm); break;
            case 5: repack_body<11>(x, b, 165, sm); break;
            case 4: repack_body<9> (x, b, 84,  sm); break;
            case 3: repack_body<7> (x, b, 35,  sm); break;
            case 2: repack_body<5> (x, b, 10,  sm); break;
            case 1: repack_body<3> (x, b, 1,   sm); break;
            default: repack_body<1>(x, b, 0,   sm); break;
        }
    }
}

// ---------------------------------------------------------------------------
// gemm: CTA = 128 rows x 64 cols, 4 warps (64x32 each), K chunks of 64,
// 2-stage cp.async, swizzled smem (128B rows), single fp16 term.
// per stage: A 128x128B = 16384 | B 64x128B = 8192 -> 24576; x2 = 49152.
// ---------------------------------------------------------------------------
#define ST      24576
#define OFF_A   0
#define OFF_B   16384
#define SM_TOT  (2 * ST)   // 49152

__global__ void __launch_bounds__(128, 4) gemm_kernel(float* __restrict__ out) {
    extern __shared__ __align__(16) char smem[];
    const uint32_t sbase = smem_u32(smem);
    __shared__ int lutS[64];

    const int tid = threadIdx.x;
    const int lane = tid & 31;
    const int wid = tid >> 5;
    const int wm = wid >> 1;      // 0..1 : 64-row band
    const int wn = wid & 1;       // 0..1 : 32-col band

    const int bid = blockIdx.x;
    int q = 0;
#pragma unroll
    for (int t = 1; t < 7; t++)
        if (bid >= P_CUM[t]) q = t;
    const int rel = bid - P_CUM[q];
    const int d  = P_D[q];
    const int off = P_OFF[q];
    const int Kl = 64 * d;
    const int bt = rel / d;
    const int jt = rel - bt * d;
    const int R0 = bt * 128;
    const int j0 = jt * 64;
    const int nc = d;                          // K chunks of 64
    const float scale = 0.125f * rsqrtf(64.0f * (float)d);

    // inline LUT: column j0+jj -> g*455 + v*d + off
    if (tid < 64) {
        int j = j0 + tid;
        int g = j / d, v = j - g * d;
        lutS[tid] = g * IRREP + v * d + off;
    }

    const int lr = tid >> 3;     // 0..15 loader row group
    const int lc = tid & 7;      // 16B chunk 0..7

    // loader base pointers (advance +64 halfs per chunk)
    const __half* pA = g_Xh + 65536L * off + (long)(R0 + lr) * Kl + lc * 8;
    const __half* pB = g_Wh + 4096L * off + (long)(j0 + lr) * Kl + lc * 8;
    uint32_t soA[8], soB[4];
#pragma unroll
    for (int i = 0; i < 8; i++) soA[i] = swz128(lr + 16 * i, lc);
#pragma unroll
    for (int i = 0; i < 4; i++) soB[i] = swz128(lr + 16 * i, lc);
    const long lstep = 16L * Kl;   // halfs between loader row-groups

    // ldmatrix addresses at ks=0 (stage-relative); ks -> ^(ks<<5)
    uint32_t addrA0[4], addrB0[2];
#pragma unroll
    for (int mf = 0; mf < 4; mf++) {
        int row = wm * 64 + mf * 16 + (lane & 15);
        addrA0[mf] = swz128(row, lane >> 4);
    }
#pragma unroll
    for (int nn = 0; nn < 2; nn++) {
        int row = wn * 32 + nn * 16 + ((lane >> 3) & 2) * 4 + (lane & 7);
        addrB0[nn] = swz128(row, (lane >> 3) & 1);
    }

    float acc[4][4][4];
#pragma unroll
    for (int mf = 0; mf < 4; mf++)
#pragma unroll
        for (int ns = 0; ns < 4; ns++)
#pragma unroll
            for (int i = 0; i < 4; i++) acc[mf][ns][i] = 0.0f;

#define ISSUE_CHUNK(s)                                                    \
    do {                                                                  \
        uint32_t sb_ = sbase + (uint32_t)((s) * ST);                      \
        _Pragma("unroll")                                                 \
        for (int i = 0; i < 8; i++)                                       \
            cpasync16(sb_ + OFF_A + soA[i], pA + i * lstep);              \
        _Pragma("unroll")                                                 \
        for (int i = 0; i < 4; i++)                                       \
            cpasync16(sb_ + OFF_B + soB[i], pB + i * lstep);              \
        pA += 64; pB += 64;                                               \
        CP_COMMIT();                                                      \
    } while (0)

    // prologue: chunk 0 into stage 0
    ISSUE_CHUNK(0);

    for (int c = 0; c < nc; c++) {
        CP_WAIT0();
        __syncthreads();   // chunk c visible; all warps done reading other stage

        if (c + 1 < nc) ISSUE_CHUNK((c + 1) & 1);   // overlaps with compute below

        const uint32_t sb = sbase + (uint32_t)((c & 1) * ST);
#pragma unroll
        for (int ks = 0; ks < 4; ks++) {
            const uint32_t kx = (uint32_t)(ks << 5);
            uint32_t a[4][4], bh[2][4];
#pragma unroll
            for (int mf = 0; mf < 4; mf++) ldsm_x4(a[mf], sb + OFF_A + (addrA0[mf] ^ kx));
#pragma unroll
            for (int nn = 0; nn < 2; nn++) ldsm_x4(bh[nn], sb + OFF_B + (addrB0[nn] ^ kx));

#pragma unroll
            for (int mf = 0; mf < 4; mf++)
#pragma unroll
                for (int ns = 0; ns < 4; ns++)
                    mma16816(acc[mf][ns], a[mf], &bh[ns >> 1][(ns & 1) * 2]);
        }
        __syncthreads();
    }

    // ---- epilogue: scale + scatter via LUT ----
#pragma unroll
    for (int mf = 0; mf < 4; mf++) {
        int row0 = R0 + wm * 64 + mf * 16 + (lane >> 2);
        int row1 = row0 + 8;
        int b0 = row0 / d, m0 = row0 - b0 * d;
        int b1 = row1 / d, m1 = row1 - b1 * d;
        long ob0 = (long)b0 * 29120 + m0;
        long ob1 = (long)b1 * 29120 + m1;
#pragma unroll
        for (int ns = 0; ns < 4; ns++) {
            int j = wn * 32 + ns * 8 + (lane & 3) * 2;
            int o0 = lutS[j], o1 = lutS[j + 1];
            out[ob0 + o0] = acc[mf][ns][0] * scale;
            out[ob0 + o1] = acc[mf][ns][1] * scale;
            out[ob1 + o0] = acc[mf][ns][2] * scale;
            out[ob1 + o1] = acc[mf][ns][3] * scale;
        }
    }
}

// ---------------------------------------------------------------------------
extern "C" void kernel_launch(void* const* d_in, const int* in_sizes, int n_in,
                              void* d_out, int out_size) {
    const float* x  = (const float*)d_in[0];
    const float* Dm = (const float*)d_in[1];
    const float* w  = (const float*)d_in[2];
    float* out = (float*)d_out;

    cudaFuncSetAttribute(prepare_kernel, cudaFuncAttributeMaxDynamicSharedMemorySize, 46912);
    cudaFuncSetAttribute(gemm_kernel, cudaFuncAttributeMaxDynamicSharedMemorySize, SM_TOT);

    prepare_kernel<<<7680, 256, 46912>>>(x, Dm, w);
    gemm_kernel<<<3640, 128, SM_TOT>>>(out);
}